// round 3
// baseline (speedup 1.0000x reference)
#include <cuda_runtime.h>
#include <cuda_bf16.h>
#include <mma.h>
#include <cstdint>

using namespace nvcuda;

// Problem constants
#define T_TOK 1024
#define H_DIM 2048
#define F_DIM 1408
#define N_EXP 16
#define K_TOP 6

// GEMM tiling
#define BM 128
#define BN 64
#define BK 32
#define LDS 36      // smem leading dim for 32-wide k tiles (pad, mult of 4)
#define LDSTG 68    // staging leading dim for 64-wide n tiles (pad, mult of 4)

// ---------------- device scratch (no allocations allowed) ----------------
__device__ int   g_counts[N_EXP];
__device__ int   g_tokens[N_EXP * T_TOK];   // token id per (expert, slot)
__device__ float g_slotw[N_EXP * T_TOK];    // routing weight per (expert, slot)
__device__ float g_act[(size_t)N_EXP * T_TOK * F_DIM];  // 92 MB SiLU(g)*u scratch

// ---------------- wmma typedefs ----------------
typedef wmma::fragment<wmma::matrix_a, 16, 16, 8, wmma::precision::tf32, wmma::row_major> FragA;
typedef wmma::fragment<wmma::matrix_b, 16, 16, 8, wmma::precision::tf32, wmma::col_major> FragB;
typedef wmma::fragment<wmma::accumulator, 16, 16, 8, float> FragC;

template <class F>
__device__ __forceinline__ void to_tf32(F& f) {
#pragma unroll
    for (int i = 0; i < f.num_elements; i++) f.x[i] = wmma::__float_to_tf32(f.x[i]);
}

// ---------------- init ----------------
__global__ void init_kernel() {
    if (threadIdx.x < N_EXP) g_counts[threadIdx.x] = 0;
}

// ---------------- router: logits -> softmax -> top6 -> scatter ----------------
__global__ __launch_bounds__(256) void router_kernel(const float* __restrict__ x,
                                                     const float* __restrict__ gw) {
    int t = blockIdx.x;
    __shared__ float slog[N_EXP];
    if (threadIdx.x < N_EXP) slog[threadIdx.x] = 0.f;
    __syncthreads();

    const float* xr = x + (size_t)t * H_DIM;
    float part[N_EXP];
#pragma unroll
    for (int e = 0; e < N_EXP; e++) part[e] = 0.f;

    for (int h = threadIdx.x; h < H_DIM; h += 256) {
        float xv = xr[h];
#pragma unroll
        for (int e = 0; e < N_EXP; e++) part[e] += xv * gw[e * H_DIM + h];
    }
#pragma unroll
    for (int e = 0; e < N_EXP; e++) {
#pragma unroll
        for (int off = 16; off; off >>= 1)
            part[e] += __shfl_down_sync(0xFFFFFFFFu, part[e], off);
    }
    if ((threadIdx.x & 31) == 0) {
#pragma unroll
        for (int e = 0; e < N_EXP; e++) atomicAdd(&slog[e], part[e]);
    }
    __syncthreads();

    if (threadIdx.x == 0) {
        float mx = -1e30f;
#pragma unroll
        for (int e = 0; e < N_EXP; e++) mx = fmaxf(mx, slog[e]);
        float p[N_EXP]; float s = 0.f;
#pragma unroll
        for (int e = 0; e < N_EXP; e++) { p[e] = __expf(slog[e] - mx); s += p[e]; }
        float inv = 1.f / s;
#pragma unroll
        for (int e = 0; e < N_EXP; e++) p[e] *= inv;

        int sel[K_TOP]; float wv[K_TOP]; float ws = 0.f;
        bool used[N_EXP];
#pragma unroll
        for (int e = 0; e < N_EXP; e++) used[e] = false;
#pragma unroll
        for (int k = 0; k < K_TOP; k++) {
            int best = -1; float bv = -1.f;
#pragma unroll
            for (int e = 0; e < N_EXP; e++)
                if (!used[e] && p[e] > bv) { bv = p[e]; best = e; }
            used[best] = true; sel[k] = best; wv[k] = bv; ws += bv;
        }
        float wsi = 1.f / ws;
#pragma unroll
        for (int k = 0; k < K_TOP; k++) {
            int e = sel[k];
            int pos = atomicAdd(&g_counts[e], 1);
            g_tokens[e * T_TOK + pos] = t;
            g_slotw[e * T_TOK + pos] = wv[k] * wsi;
        }
    }
}

// ---------------- GEMM1: gathered x @ wv1^T, fused SiLU(g)*u ----------------
// grid: (F/BN=22, T/BM=8, E=16); block 256 (8 warps as 4m x 2n, warp tile 32x32)
__global__ __launch_bounds__(256) void gemm1_kernel(const float* __restrict__ x,
                                                    const float* __restrict__ wv1) {
    __shared__ float smem[BM * LDS + 2 * BN * LDS];  // 9216 floats; reused as 128x68 stage
    __shared__ int stok[BM];

    int e = blockIdx.z;
    int ne = g_counts[e];
    int m0 = blockIdx.y * BM;
    if (m0 >= ne) return;
    int n0 = blockIdx.x * BN;

    int tid = threadIdx.x;
    int wid = tid >> 5;
    int wm = wid >> 1;      // 0..3
    int wn = wid & 1;       // 0..1

    float* sA  = smem;
    float* sBg = smem + BM * LDS;
    float* sBu = sBg + BN * LDS;

    for (int i = tid; i < BM; i += 256)
        stok[i] = (m0 + i < ne) ? g_tokens[e * T_TOK + m0 + i] : -1;
    __syncthreads();

    FragC cg[2][2], cu[2][2];
#pragma unroll
    for (int i = 0; i < 2; i++)
#pragma unroll
        for (int j = 0; j < 2; j++) {
            wmma::fill_fragment(cg[i][j], 0.f);
            wmma::fill_fragment(cu[i][j], 0.f);
        }

    const float* wg = wv1 + ((size_t)e * 2 * F_DIM + n0) * H_DIM;
    const float* wu = wv1 + ((size_t)e * 2 * F_DIM + F_DIM + n0) * H_DIM;

    for (int k0 = 0; k0 < H_DIM; k0 += BK) {
        // A tile: 128 x 32 gathered rows of x
        for (int idx = tid; idx < BM * 8; idx += 256) {
            int r = idx >> 3, c = (idx & 7) * 4;
            int tok = stok[r];
            float4 v = make_float4(0.f, 0.f, 0.f, 0.f);
            if (tok >= 0) v = *(const float4*)(x + (size_t)tok * H_DIM + k0 + c);
            *(float4*)(sA + r * LDS + c) = v;
        }
        // B tiles: gate half and up half, 64 x 32 each
        for (int idx = tid; idx < BN * 8; idx += 256) {
            int r = idx >> 3, c = (idx & 7) * 4;
            *(float4*)(sBg + r * LDS + c) = *(const float4*)(wg + (size_t)r * H_DIM + k0 + c);
            *(float4*)(sBu + r * LDS + c) = *(const float4*)(wu + (size_t)r * H_DIM + k0 + c);
        }
        __syncthreads();

#pragma unroll
        for (int ks = 0; ks < BK; ks += 8) {
            FragA a[2]; FragB bg[2], bu[2];
#pragma unroll
            for (int i = 0; i < 2; i++) {
                wmma::load_matrix_sync(a[i], sA + (wm * 32 + i * 16) * LDS + ks, LDS);
                to_tf32(a[i]);
            }
#pragma unroll
            for (int j = 0; j < 2; j++) {
                wmma::load_matrix_sync(bg[j], sBg + (wn * 32 + j * 16) * LDS + ks, LDS);
                to_tf32(bg[j]);
                wmma::load_matrix_sync(bu[j], sBu + (wn * 32 + j * 16) * LDS + ks, LDS);
                to_tf32(bu[j]);
            }
#pragma unroll
            for (int i = 0; i < 2; i++)
#pragma unroll
                for (int j = 0; j < 2; j++) {
                    wmma::mma_sync(cg[i][j], a[i], bg[j], cg[i][j]);
                    wmma::mma_sync(cu[i][j], a[i], bu[j], cu[i][j]);
                }
        }
        __syncthreads();
    }

    // epilogue: act = silu(g) * u, stage in smem, guarded store to g_act
    float* stage = smem;  // 128 x 68
#pragma unroll
    for (int i = 0; i < 2; i++)
#pragma unroll
        for (int j = 0; j < 2; j++) {
#pragma unroll
            for (int el = 0; el < cg[i][j].num_elements; el++) {
                float gv = cg[i][j].x[el];
                float uv = cu[i][j].x[el];
                cg[i][j].x[el] = (gv / (1.f + __expf(-gv))) * uv;
            }
            wmma::store_matrix_sync(stage + (wm * 32 + i * 16) * LDSTG + wn * 32 + j * 16,
                                    cg[i][j], LDSTG, wmma::mem_row_major);
        }
    __syncthreads();

    for (int idx = tid; idx < BM * 16; idx += 256) {
        int r = idx >> 4, c = (idx & 15) * 4;
        if (m0 + r < ne)
            *(float4*)(g_act + ((size_t)e * T_TOK + m0 + r) * F_DIM + n0 + c) =
                *(float4*)(stage + r * LDSTG + c);
    }
}

// ---------------- GEMM2: act @ w2^T, fused weighted scatter to out ----------------
// grid: (H/BN=32, T/BM=8, E=16); block 256
__global__ __launch_bounds__(256) void gemm2_kernel(const float* __restrict__ w2,
                                                    float* __restrict__ out) {
    __shared__ float smem[BM * LDSTG];  // 8704 floats: load region (6912) / stage (8704)
    __shared__ int   stok[BM];
    __shared__ float swt[BM];

    int e = blockIdx.z;
    int ne = g_counts[e];
    int m0 = blockIdx.y * BM;
    if (m0 >= ne) return;
    int n0 = blockIdx.x * BN;

    int tid = threadIdx.x;
    int wid = tid >> 5;
    int wm = wid >> 1;
    int wn = wid & 1;

    float* sA = smem;
    float* sB = smem + BM * LDS;

    for (int i = tid; i < BM; i += 256) {
        bool ok = (m0 + i < ne);
        stok[i] = ok ? g_tokens[e * T_TOK + m0 + i] : -1;
        swt[i]  = ok ? g_slotw[e * T_TOK + m0 + i] : 0.f;
    }
    __syncthreads();

    FragC c[2][2];
#pragma unroll
    for (int i = 0; i < 2; i++)
#pragma unroll
        for (int j = 0; j < 2; j++) wmma::fill_fragment(c[i][j], 0.f);

    const float* Abase = g_act + ((size_t)e * T_TOK + m0) * F_DIM;
    const float* Bbase = w2 + ((size_t)e * H_DIM + n0) * F_DIM;

    for (int k0 = 0; k0 < F_DIM; k0 += BK) {
        for (int idx = tid; idx < BM * 8; idx += 256) {
            int r = idx >> 3, cc = (idx & 7) * 4;
            float4 v = make_float4(0.f, 0.f, 0.f, 0.f);
            if (m0 + r < ne) v = *(const float4*)(Abase + (size_t)r * F_DIM + k0 + cc);
            *(float4*)(sA + r * LDS + cc) = v;
        }
        for (int idx = tid; idx < BN * 8; idx += 256) {
            int r = idx >> 3, cc = (idx & 7) * 4;
            *(float4*)(sB + r * LDS + cc) = *(const float4*)(Bbase + (size_t)r * F_DIM + k0 + cc);
        }
        __syncthreads();

#pragma unroll
        for (int ks = 0; ks < BK; ks += 8) {
            FragA a[2]; FragB b[2];
#pragma unroll
            for (int i = 0; i < 2; i++) {
                wmma::load_matrix_sync(a[i], sA + (wm * 32 + i * 16) * LDS + ks, LDS);
                to_tf32(a[i]);
            }
#pragma unroll
            for (int j = 0; j < 2; j++) {
                wmma::load_matrix_sync(b[j], sB + (wn * 32 + j * 16) * LDS + ks, LDS);
                to_tf32(b[j]);
            }
#pragma unroll
            for (int i = 0; i < 2; i++)
#pragma unroll
                for (int j = 0; j < 2; j++)
                    wmma::mma_sync(c[i][j], a[i], b[j], c[i][j]);
        }
        __syncthreads();
    }

    // epilogue: stage, then weighted atomic scatter into out[t, h]
    float* stage = smem;
#pragma unroll
    for (int i = 0; i < 2; i++)
#pragma unroll
        for (int j = 0; j < 2; j++)
            wmma::store_matrix_sync(stage + (wm * 32 + i * 16) * LDSTG + wn * 32 + j * 16,
                                    c[i][j], LDSTG, wmma::mem_row_major);
    __syncthreads();

    for (int idx = tid; idx < BM * 16; idx += 256) {
        int r = idx >> 4, cc = (idx & 15) * 4;
        if (m0 + r < ne) {
            int t = stok[r];
            float w = swt[r];
            float4 v = *(float4*)(stage + r * LDSTG + cc);
            float* o = out + (size_t)t * H_DIM + n0 + cc;
            atomicAdd(o + 0, w * v.x);
            atomicAdd(o + 1, w * v.y);
            atomicAdd(o + 2, w * v.z);
            atomicAdd(o + 3, w * v.w);
        }
    }
}

// ---------------- launch ----------------
extern "C" void kernel_launch(void* const* d_in, const int* in_sizes, int n_in,
                              void* d_out, int out_size) {
    (void)in_sizes; (void)n_in;
    const float* x    = (const float*)d_in[0];
    const float* gw   = (const float*)d_in[1];
    const float* wv1  = (const float*)d_in[2];
    const float* w2   = (const float*)d_in[3];
    float* out = (float*)d_out;

    cudaMemsetAsync(out, 0, (size_t)out_size * sizeof(float));
    init_kernel<<<1, 32>>>();
    router_kernel<<<T_TOK, 256>>>(x, gw);
    gemm1_kernel<<<dim3(F_DIM / BN, T_TOK / BM, N_EXP), 256>>>(x, wv1);
    gemm2_kernel<<<dim3(H_DIM / BN, T_TOK / BM, N_EXP), 256>>>(w2, out);
}

// round 4
// speedup vs baseline: 1.8456x; 1.8456x over previous
#include <cuda_runtime.h>
#include <cuda_bf16.h>
#include <mma.h>
#include <cstdint>

using namespace nvcuda;

// Problem constants
#define T_TOK 1024
#define H_DIM 2048
#define F_DIM 1408
#define N_EXP 16
#define K_TOP 6

// GEMM tiling
#define BM 128
#define BN 64
#define BK 32
#define LDS 36      // smem leading dim (floats) for 32-wide k tiles; 144B, 16B-aligned chunks
#define LDSTG 68    // staging leading dim for 64-wide n tiles

// Per-stage smem sizes (floats)
#define G1_STAGE (BM * LDS + 2 * BN * LDS)   // 9216
#define G2_STAGE (BM * LDS + BN * LDS)       // 6912

// ---------------- device scratch (no allocations allowed) ----------------
__device__ int   g_counts[N_EXP];
__device__ int   g_tokens[N_EXP * T_TOK];
__device__ float g_slotw[N_EXP * T_TOK];
__device__ float g_act[(size_t)N_EXP * T_TOK * F_DIM];  // 92 MB SiLU(g)*u scratch

// ---------------- wmma typedefs ----------------
typedef wmma::fragment<wmma::matrix_a, 16, 16, 8, wmma::precision::tf32, wmma::row_major> FragA;
typedef wmma::fragment<wmma::matrix_b, 16, 16, 8, wmma::precision::tf32, wmma::col_major> FragB;
typedef wmma::fragment<wmma::accumulator, 16, 16, 8, float> FragC;

template <class F>
__device__ __forceinline__ void to_tf32(F& f) {
#pragma unroll
    for (int i = 0; i < f.num_elements; i++) f.x[i] = wmma::__float_to_tf32(f.x[i]);
}

// ---------------- cp.async helpers ----------------
__device__ __forceinline__ void cp16(void* dst, const float* src, int sz) {
    uint32_t d = (uint32_t)__cvta_generic_to_shared(dst);
    asm volatile("cp.async.cg.shared.global [%0], [%1], 16, %2;" :: "r"(d), "l"(src), "r"(sz));
}
#define CP_COMMIT() asm volatile("cp.async.commit_group;")
#define CP_WAIT1()  asm volatile("cp.async.wait_group 1;")
#define CP_WAIT0()  asm volatile("cp.async.wait_group 0;")

// ---------------- init ----------------
__global__ void init_kernel() {
    if (threadIdx.x < N_EXP) g_counts[threadIdx.x] = 0;
}

// ---------------- router: logits -> softmax -> top6 -> scatter ----------------
__global__ __launch_bounds__(256) void router_kernel(const float* __restrict__ x,
                                                     const float* __restrict__ gw) {
    int t = blockIdx.x;
    __shared__ float slog[N_EXP];
    if (threadIdx.x < N_EXP) slog[threadIdx.x] = 0.f;
    __syncthreads();

    const float* xr = x + (size_t)t * H_DIM;
    float part[N_EXP];
#pragma unroll
    for (int e = 0; e < N_EXP; e++) part[e] = 0.f;

    for (int h = threadIdx.x; h < H_DIM; h += 256) {
        float xv = xr[h];
#pragma unroll
        for (int e = 0; e < N_EXP; e++) part[e] += xv * gw[e * H_DIM + h];
    }
#pragma unroll
    for (int e = 0; e < N_EXP; e++) {
#pragma unroll
        for (int off = 16; off; off >>= 1)
            part[e] += __shfl_down_sync(0xFFFFFFFFu, part[e], off);
    }
    if ((threadIdx.x & 31) == 0) {
#pragma unroll
        for (int e = 0; e < N_EXP; e++) atomicAdd(&slog[e], part[e]);
    }
    __syncthreads();

    if (threadIdx.x == 0) {
        float mx = -1e30f;
#pragma unroll
        for (int e = 0; e < N_EXP; e++) mx = fmaxf(mx, slog[e]);
        float p[N_EXP]; float s = 0.f;
#pragma unroll
        for (int e = 0; e < N_EXP; e++) { p[e] = __expf(slog[e] - mx); s += p[e]; }
        float inv = 1.f / s;
#pragma unroll
        for (int e = 0; e < N_EXP; e++) p[e] *= inv;

        int sel[K_TOP]; float wv[K_TOP]; float ws = 0.f;
        bool used[N_EXP];
#pragma unroll
        for (int e = 0; e < N_EXP; e++) used[e] = false;
#pragma unroll
        for (int k = 0; k < K_TOP; k++) {
            int best = -1; float bv = -1.f;
#pragma unroll
            for (int e = 0; e < N_EXP; e++)
                if (!used[e] && p[e] > bv) { bv = p[e]; best = e; }
            used[best] = true; sel[k] = best; wv[k] = bv; ws += bv;
        }
        float wsi = 1.f / ws;
#pragma unroll
        for (int k = 0; k < K_TOP; k++) {
            int e = sel[k];
            int pos = atomicAdd(&g_counts[e], 1);
            g_tokens[e * T_TOK + pos] = t;
            g_slotw[e * T_TOK + pos] = wv[k] * wsi;
        }
    }
}

// ---------------- GEMM1: gathered x @ wv1^T, fused SiLU(g)*u, 2-stage cp.async ----------------
// grid: (F/BN=22, T/BM=8, E=16); block 256 (8 warps as 4m x 2n, warp tile 32x32 over g and u)
__global__ __launch_bounds__(256, 2) void gemm1_kernel(const float* __restrict__ x,
                                                       const float* __restrict__ wv1) {
    extern __shared__ float smem[];          // 2 * G1_STAGE floats
    __shared__ int stok[BM];

    int e = blockIdx.z;
    int ne = g_counts[e];
    int m0 = blockIdx.y * BM;
    if (m0 >= ne) return;
    int n0 = blockIdx.x * BN;

    int tid = threadIdx.x;
    int wid = tid >> 5;
    int wm = wid >> 1;      // 0..3
    int wn = wid & 1;       // 0..1

    for (int i = tid; i < BM; i += 256)
        stok[i] = (m0 + i < ne) ? g_tokens[e * T_TOK + m0 + i] : -1;
    __syncthreads();

    const float* wg = wv1 + ((size_t)e * 2 * F_DIM + n0) * H_DIM;
    const float* wu = wv1 + ((size_t)e * 2 * F_DIM + F_DIM + n0) * H_DIM;

#define G1_ISSUE(k0, s) do {                                                          \
    float* sA_  = smem + (s) * G1_STAGE;                                              \
    float* sBg_ = sA_ + BM * LDS;                                                     \
    float* sBu_ = sBg_ + BN * LDS;                                                    \
    _Pragma("unroll")                                                                 \
    for (int j_ = 0; j_ < 4; j_++) {                                                  \
        int idx_ = tid + j_ * 256; int r_ = idx_ >> 3, c_ = (idx_ & 7) * 4;           \
        int tok_ = stok[r_];                                                          \
        const float* src_ = x + (size_t)(tok_ < 0 ? 0 : tok_) * H_DIM + (k0) + c_;    \
        cp16(sA_ + r_ * LDS + c_, src_, tok_ < 0 ? 0 : 16);                           \
    }                                                                                 \
    _Pragma("unroll")                                                                 \
    for (int j_ = 0; j_ < 2; j_++) {                                                  \
        int idx_ = tid + j_ * 256; int r_ = idx_ >> 3, c_ = (idx_ & 7) * 4;           \
        cp16(sBg_ + r_ * LDS + c_, wg + (size_t)r_ * H_DIM + (k0) + c_, 16);          \
        cp16(sBu_ + r_ * LDS + c_, wu + (size_t)r_ * H_DIM + (k0) + c_, 16);          \
    }                                                                                 \
    CP_COMMIT();                                                                      \
} while (0)

    FragC cg[2][2], cu[2][2];
#pragma unroll
    for (int i = 0; i < 2; i++)
#pragma unroll
        for (int j = 0; j < 2; j++) {
            wmma::fill_fragment(cg[i][j], 0.f);
            wmma::fill_fragment(cu[i][j], 0.f);
        }

    const int NT = H_DIM / BK;   // 64
    G1_ISSUE(0, 0);

    for (int it = 0; it < NT; ++it) {
        int s = it & 1;
        if (it + 1 < NT) { G1_ISSUE((it + 1) * BK, s ^ 1); CP_WAIT1(); }
        else             { CP_WAIT0(); }
        __syncthreads();

        float* sA  = smem + s * G1_STAGE;
        float* sBg = sA + BM * LDS;
        float* sBu = sBg + BN * LDS;

#pragma unroll
        for (int ks = 0; ks < BK; ks += 8) {
            FragA a[2]; FragB bg[2], bu[2];
#pragma unroll
            for (int i = 0; i < 2; i++) {
                wmma::load_matrix_sync(a[i], sA + (wm * 32 + i * 16) * LDS + ks, LDS);
                to_tf32(a[i]);
            }
#pragma unroll
            for (int j = 0; j < 2; j++) {
                wmma::load_matrix_sync(bg[j], sBg + (wn * 32 + j * 16) * LDS + ks, LDS);
                to_tf32(bg[j]);
                wmma::load_matrix_sync(bu[j], sBu + (wn * 32 + j * 16) * LDS + ks, LDS);
                to_tf32(bu[j]);
            }
#pragma unroll
            for (int i = 0; i < 2; i++)
#pragma unroll
                for (int j = 0; j < 2; j++) {
                    wmma::mma_sync(cg[i][j], a[i], bg[j], cg[i][j]);
                    wmma::mma_sync(cu[i][j], a[i], bu[j], cu[i][j]);
                }
        }
        __syncthreads();
    }
#undef G1_ISSUE

    // epilogue: act = silu(g) * u, stage in smem, guarded store to g_act
    float* stage = smem;  // 128 x 68 (8704 floats, fits in stage area)
#pragma unroll
    for (int i = 0; i < 2; i++)
#pragma unroll
        for (int j = 0; j < 2; j++) {
#pragma unroll
            for (int el = 0; el < cg[i][j].num_elements; el++) {
                float gv = cg[i][j].x[el];
                float uv = cu[i][j].x[el];
                cg[i][j].x[el] = (gv / (1.f + __expf(-gv))) * uv;
            }
            wmma::store_matrix_sync(stage + (wm * 32 + i * 16) * LDSTG + wn * 32 + j * 16,
                                    cg[i][j], LDSTG, wmma::mem_row_major);
        }
    __syncthreads();

    for (int idx = tid; idx < BM * 16; idx += 256) {
        int r = idx >> 4, c = (idx & 15) * 4;
        if (m0 + r < ne)
            *(float4*)(g_act + ((size_t)e * T_TOK + m0 + r) * F_DIM + n0 + c) =
                *(float4*)(stage + r * LDSTG + c);
    }
}

// ---------------- GEMM2: act @ w2^T, fused weighted scatter, 2-stage cp.async ----------------
// grid: (H/BN=32, T/BM=8, E=16); block 256
__global__ __launch_bounds__(256, 2) void gemm2_kernel(const float* __restrict__ w2,
                                                       float* __restrict__ out) {
    extern __shared__ float smem[];          // 2 * G2_STAGE floats
    __shared__ int   stok[BM];
    __shared__ float swt[BM];

    int e = blockIdx.z;
    int ne = g_counts[e];
    int m0 = blockIdx.y * BM;
    if (m0 >= ne) return;
    int n0 = blockIdx.x * BN;

    int tid = threadIdx.x;
    int wid = tid >> 5;
    int wm = wid >> 1;
    int wn = wid & 1;

    for (int i = tid; i < BM; i += 256) {
        bool ok = (m0 + i < ne);
        stok[i] = ok ? g_tokens[e * T_TOK + m0 + i] : -1;
        swt[i]  = ok ? g_slotw[e * T_TOK + m0 + i] : 0.f;
    }
    __syncthreads();

    const float* Abase = g_act + ((size_t)e * T_TOK + m0) * F_DIM;
    const float* Bbase = w2 + ((size_t)e * H_DIM + n0) * F_DIM;
    int nrows = ne - m0;   // >0 here

#define G2_ISSUE(k0, s) do {                                                          \
    float* sA_ = smem + (s) * G2_STAGE;                                               \
    float* sB_ = sA_ + BM * LDS;                                                      \
    _Pragma("unroll")                                                                 \
    for (int j_ = 0; j_ < 4; j_++) {                                                  \
        int idx_ = tid + j_ * 256; int r_ = idx_ >> 3, c_ = (idx_ & 7) * 4;           \
        bool ok_ = (r_ < nrows);                                                      \
        const float* src_ = Abase + (size_t)(ok_ ? r_ : 0) * F_DIM + (k0) + c_;       \
        cp16(sA_ + r_ * LDS + c_, src_, ok_ ? 16 : 0);                                \
    }                                                                                 \
    _Pragma("unroll")                                                                 \
    for (int j_ = 0; j_ < 2; j_++) {                                                  \
        int idx_ = tid + j_ * 256; int r_ = idx_ >> 3, c_ = (idx_ & 7) * 4;           \
        cp16(sB_ + r_ * LDS + c_, Bbase + (size_t)r_ * F_DIM + (k0) + c_, 16);        \
    }                                                                                 \
    CP_COMMIT();                                                                      \
} while (0)

    FragC c[2][2];
#pragma unroll
    for (int i = 0; i < 2; i++)
#pragma unroll
        for (int j = 0; j < 2; j++) wmma::fill_fragment(c[i][j], 0.f);

    const int NT = F_DIM / BK;   // 44
    G2_ISSUE(0, 0);

    for (int it = 0; it < NT; ++it) {
        int s = it & 1;
        if (it + 1 < NT) { G2_ISSUE((it + 1) * BK, s ^ 1); CP_WAIT1(); }
        else             { CP_WAIT0(); }
        __syncthreads();

        float* sA = smem + s * G2_STAGE;
        float* sB = sA + BM * LDS;

#pragma unroll
        for (int ks = 0; ks < BK; ks += 8) {
            FragA a[2]; FragB b[2];
#pragma unroll
            for (int i = 0; i < 2; i++) {
                wmma::load_matrix_sync(a[i], sA + (wm * 32 + i * 16) * LDS + ks, LDS);
                to_tf32(a[i]);
            }
#pragma unroll
            for (int j = 0; j < 2; j++) {
                wmma::load_matrix_sync(b[j], sB + (wn * 32 + j * 16) * LDS + ks, LDS);
                to_tf32(b[j]);
            }
#pragma unroll
            for (int i = 0; i < 2; i++)
#pragma unroll
                for (int j = 0; j < 2; j++)
                    wmma::mma_sync(c[i][j], a[i], b[j], c[i][j]);
        }
        __syncthreads();
    }
#undef G2_ISSUE

    // epilogue: stage, then weighted atomic scatter into out[t, h]
    float* stage = smem;   // 8704 floats fits in 2*G2_STAGE = 13824
#pragma unroll
    for (int i = 0; i < 2; i++)
#pragma unroll
        for (int j = 0; j < 2; j++)
            wmma::store_matrix_sync(stage + (wm * 32 + i * 16) * LDSTG + wn * 32 + j * 16,
                                    c[i][j], LDSTG, wmma::mem_row_major);
    __syncthreads();

    for (int idx = tid; idx < BM * 16; idx += 256) {
        int r = idx >> 4, cc = (idx & 15) * 4;
        if (r < nrows) {
            int t = stok[r];
            float w = swt[r];
            float4 v = *(float4*)(stage + r * LDSTG + cc);
            float* o = out + (size_t)t * H_DIM + n0 + cc;
            atomicAdd(o + 0, w * v.x);
            atomicAdd(o + 1, w * v.y);
            atomicAdd(o + 2, w * v.z);
            atomicAdd(o + 3, w * v.w);
        }
    }
}

// ---------------- launch ----------------
extern "C" void kernel_launch(void* const* d_in, const int* in_sizes, int n_in,
                              void* d_out, int out_size) {
    (void)in_sizes; (void)n_in;
    const float* x    = (const float*)d_in[0];
    const float* gw   = (const float*)d_in[1];
    const float* wv1  = (const float*)d_in[2];
    const float* w2   = (const float*)d_in[3];
    float* out = (float*)d_out;

    const int g1_smem = 2 * G1_STAGE * (int)sizeof(float);   // 73728 B
    const int g2_smem = 2 * G2_STAGE * (int)sizeof(float);   // 55296 B
    static bool attr_set = false;
    if (!attr_set) {
        cudaFuncSetAttribute(gemm1_kernel, cudaFuncAttributeMaxDynamicSharedMemorySize, g1_smem);
        cudaFuncSetAttribute(gemm2_kernel, cudaFuncAttributeMaxDynamicSharedMemorySize, g2_smem);
        attr_set = true;
    }

    cudaMemsetAsync(out, 0, (size_t)out_size * sizeof(float));
    init_kernel<<<1, 32>>>();
    router_kernel<<<T_TOK, 256>>>(x, gw);
    gemm1_kernel<<<dim3(F_DIM / BN, T_TOK / BM, N_EXP), 256, g1_smem>>>(x, wv1);
    gemm2_kernel<<<dim3(H_DIM / BN, T_TOK / BM, N_EXP), 256, g2_smem>>>(w2, out);
}